// round 2
// baseline (speedup 1.0000x reference)
#include <cuda_runtime.h>

#define N_NODES 50000
#define N_EDGES 800000
#define DIM 96

// Scratch (allocation-free rule: __device__ globals)
__device__ float g_agg[N_NODES * DIM];   // 19.2 MB
__device__ float g_deg[N_NODES];

// ---------------------------------------------------------------------------
// Kernel 1: zero the accumulators
// ---------------------------------------------------------------------------
__global__ void zero_kernel() {
    int tid = blockIdx.x * blockDim.x + threadIdx.x;
    int stride = gridDim.x * blockDim.x;
    const int total_agg = N_NODES * DIM;
    for (int i = tid; i < total_agg; i += stride) g_agg[i] = 0.0f;
    for (int i = tid; i < N_NODES; i += stride) g_deg[i] = 0.0f;
}

// ---------------------------------------------------------------------------
// Kernel 2: edge scatter — one warp per edge.
// edge_index is int32 (JAX default x64-disabled downcasts the declared int64).
// Lanes 0..31 cover DIM=96 in 3 strided passes (coalesced LDG + atomicAdd).
// ---------------------------------------------------------------------------
__global__ void scatter_kernel(const float* __restrict__ x,
                               const int* __restrict__ edge_index) {
    int gtid = blockIdx.x * blockDim.x + threadIdx.x;
    int warp = gtid >> 5;
    int lane = gtid & 31;
    if (warp >= N_EDGES) return;

    int src = edge_index[warp];            // edge_index[0][e]
    int dst = edge_index[N_EDGES + warp];  // edge_index[1][e]

    const float* __restrict__ xr = x + (size_t)src * DIM;
    float* __restrict__ ar = g_agg + (size_t)dst * DIM;

    #pragma unroll
    for (int k = 0; k < 3; k++) {
        int idx = lane + k * 32;
        atomicAdd(&ar[idx], xr[idx]);
    }
    if (lane == 0) atomicAdd(&g_deg[dst], 1.0f);
}

// ---------------------------------------------------------------------------
// Kernel 3: fused mean + dual GEMM + biases.
// out[i,:] = x[i,:] @ Ws^T + bs + (agg[i,:]/max(deg,1)) @ Wn^T + bn
// Block: (96, ROWS) threads. Weights staged in dynamic shared memory.
// Thread (j, y) computes out[row(y), j].
// ---------------------------------------------------------------------------
#define ROWS 4
#define WPITCH 97   // 96 + 1 pad: j*97 stride is conflict-free across 32 banks

__global__ void sage_kernel(const float* __restrict__ x,
                            const float* __restrict__ W_self,
                            const float* __restrict__ b_self,
                            const float* __restrict__ W_neigh,
                            const float* __restrict__ b_neigh,
                            float* __restrict__ out) {
    extern __shared__ float smem[];
    float* sWs = smem;                       // [96][97]
    float* sWn = sWs + DIM * WPITCH;         // [96][97]
    float* sx  = sWn + DIM * WPITCH;         // [ROWS][96]
    float* sm  = sx + ROWS * DIM;            // [ROWS][96]

    const int j   = threadIdx.x;             // 0..95 (output feature)
    const int y   = threadIdx.y;             // 0..ROWS-1
    const int tid = y * DIM + j;
    const int nthreads = ROWS * DIM;

    // Stage both weight matrices (row-major [out_feat][in_feat]) into smem.
    for (int i = tid; i < DIM * DIM; i += nthreads) {
        int r = i / DIM, c = i % DIM;
        sWs[r * WPITCH + c] = W_self[i];
        sWn[r * WPITCH + c] = W_neigh[i];
    }

    const int row = blockIdx.x * ROWS + y;   // node index (grid sized exactly)

    // Stage this block's x rows and neighbor-mean rows.
    {
        float d = g_deg[row];
        float inv = 1.0f / fmaxf(d, 1.0f);
        sx[y * DIM + j] = x[(size_t)row * DIM + j];
        sm[y * DIM + j] = g_agg[(size_t)row * DIM + j] * inv;
    }
    __syncthreads();

    float acc = b_self[j] + b_neigh[j];
    const float* ws = sWs + j * WPITCH;
    const float* wn = sWn + j * WPITCH;
    const float* xv = sx + y * DIM;
    const float* mv = sm + y * DIM;

    #pragma unroll
    for (int k = 0; k < DIM; k++) {
        acc += xv[k] * ws[k] + mv[k] * wn[k];
    }

    out[(size_t)row * DIM + j] = acc;
}

// ---------------------------------------------------------------------------
extern "C" void kernel_launch(void* const* d_in, const int* in_sizes, int n_in,
                              void* d_out, int out_size) {
    const float* x        = (const float*)d_in[0];
    const int*   ei       = (const int*)d_in[1];
    const float* W_self   = (const float*)d_in[2];
    const float* b_self   = (const float*)d_in[3];
    const float* W_neigh  = (const float*)d_in[4];
    const float* b_neigh  = (const float*)d_in[5];
    float*       out      = (float*)d_out;

    // 1) zero scratch
    zero_kernel<<<4096, 256>>>();

    // 2) scatter: one warp per edge -> 800000 warps
    {
        int threads = 256;
        long long total_threads = (long long)N_EDGES * 32;
        int blocks = (int)((total_threads + threads - 1) / threads);
        scatter_kernel<<<blocks, threads>>>(x, ei);
    }

    // 3) fused mean + GEMM
    {
        static bool attr_set = false;
        size_t smem_bytes = (size_t)(2 * DIM * WPITCH + 2 * ROWS * DIM) * sizeof(float);
        if (!attr_set) {
            cudaFuncSetAttribute(sage_kernel,
                                 cudaFuncAttributeMaxDynamicSharedMemorySize,
                                 (int)smem_bytes);
            attr_set = true;
        }
        dim3 block(DIM, ROWS);
        dim3 grid(N_NODES / ROWS);   // 50000 / 4 = 12500, exact
        sage_kernel<<<grid, block, smem_bytes>>>(x, W_self, b_self, W_neigh, b_neigh, out);
    }
}

// round 3
// speedup vs baseline: 2.1735x; 2.1735x over previous
#include <cuda_runtime.h>

#define N_NODES 50000
#define N_EDGES 800000
#define DIM 96
#define K2 192   // concatenated K: [x | neighbor_mean]

// Scratch (__device__ globals per allocation-free rule)
__device__ __align__(128) float g_agg[N_NODES * DIM];   // 19.2 MB
__device__ float g_deg[N_NODES];
__device__ __align__(128) float g_Bt[K2 * DIM];          // transposed weights [k][j]
__device__ float g_bias[DIM];

// ---------------------------------------------------------------------------
// Kernel 1: zero the accumulators
// ---------------------------------------------------------------------------
__global__ void zero_kernel() {
    int tid = blockIdx.x * blockDim.x + threadIdx.x;
    int stride = gridDim.x * blockDim.x;
    const int total_agg = N_NODES * DIM;
    for (int i = tid; i < total_agg; i += stride) g_agg[i] = 0.0f;
    for (int i = tid; i < N_NODES; i += stride) g_deg[i] = 0.0f;
}

// ---------------------------------------------------------------------------
// Kernel 2: prep — transpose [Ws | Wn] into k-major g_Bt, fuse biases.
// g_Bt[k][j] = (k < 96) ? Ws[j][k] : Wn[j][k-96]
// ---------------------------------------------------------------------------
__global__ void prep_kernel(const float* __restrict__ Ws, const float* __restrict__ Wn,
                            const float* __restrict__ bs, const float* __restrict__ bn) {
    int t = blockIdx.x * blockDim.x + threadIdx.x;
    if (t < K2 * DIM) {
        int k = t / DIM, j = t % DIM;
        g_Bt[t] = (k < DIM) ? Ws[j * DIM + k] : Wn[j * DIM + (k - DIM)];
    }
    if (t < DIM) g_bias[t] = bs[t] + bn[t];
}

// ---------------------------------------------------------------------------
// Kernel 3: edge scatter — one thread per (edge, 16B chunk). 24 chunks/edge.
// 128-bit vector reduction (red.global.add.v4.f32, sm_90+).
// ---------------------------------------------------------------------------
__global__ void scatter_kernel(const float* __restrict__ x,
                               const int* __restrict__ edge_index) {
    long long t = (long long)blockIdx.x * blockDim.x + threadIdx.x;
    int e = (int)(t / 24);
    int c = (int)(t % 24);
    if (e >= N_EDGES) return;

    int src = edge_index[e];            // edge_index[0][e]
    int dst = edge_index[N_EDGES + e];  // edge_index[1][e]

    float4 v = ((const float4*)(x + (size_t)src * DIM))[c];
    float* p = g_agg + (size_t)dst * DIM + c * 4;
    asm volatile("red.global.add.v4.f32 [%0], {%1,%2,%3,%4};"
                 :: "l"(p), "f"(v.x), "f"(v.y), "f"(v.z), "f"(v.w) : "memory");
    if (c == 0) atomicAdd(&g_deg[dst], 1.0f);
}

// ---------------------------------------------------------------------------
// Kernel 4: normalize g_agg rows by max(degree, 1)  (float4-vectorized)
// ---------------------------------------------------------------------------
__global__ void normalize_kernel() {
    int t = blockIdx.x * blockDim.x + threadIdx.x;
    if (t >= N_NODES * 24) return;
    int row = t / 24;
    float inv = 1.0f / fmaxf(g_deg[row], 1.0f);
    float4* p = (float4*)g_agg + t;
    float4 v = *p;
    v.x *= inv; v.y *= inv; v.z *= inv; v.w *= inv;
    *p = v;
}

// ---------------------------------------------------------------------------
// Kernel 5: register-tiled GEMM. out[50000,96] = A[50000,192] @ g_Bt + bias
// where A = [x | normalized g_agg]. BM=64, BN=96, BK=32; thread tile 8x4;
// 192 threads/block.
// ---------------------------------------------------------------------------
#define BM 64
#define BN 96
#define BK 32
#define TM 8
#define TN 4
#define GEMM_THREADS 192

__global__ __launch_bounds__(GEMM_THREADS)
void gemm_kernel(const float* __restrict__ x, float* __restrict__ out) {
    __shared__ float sA[BM][BK + 1];   // +1 pad: conflict-free column reads
    __shared__ float sB[BK][BN];       // [k][j]; rows 384B -> float4-aligned

    const int tid = threadIdx.x;
    const int tx = tid % (BN / TN);    // 0..23 column group
    const int ty = tid / (BN / TN);    // 0..7  row group
    const int rowBase = blockIdx.x * BM;

    float acc[TM][TN];
    #pragma unroll
    for (int i = 0; i < TM; i++)
        #pragma unroll
        for (int j = 0; j < TN; j++) acc[i][j] = 0.0f;

    for (int k0 = 0; k0 < K2; k0 += BK) {
        const float* __restrict__ Asrc = (k0 < DIM) ? x : g_agg;
        const int kOff = (k0 < DIM) ? k0 : (k0 - DIM);

        // Load A chunk: 64 rows x 32 k = 512 float4s across 192 threads.
        #pragma unroll
        for (int idx = tid; idx < BM * BK / 4; idx += GEMM_THREADS) {
            int m  = idx >> 3;        // 8 float4s per row
            int kq = idx & 7;
            int row = rowBase + m;
            float4 v = make_float4(0.f, 0.f, 0.f, 0.f);
            if (row < N_NODES)
                v = ((const float4*)(Asrc + (size_t)row * DIM + kOff))[kq];
            sA[m][kq * 4 + 0] = v.x;
            sA[m][kq * 4 + 1] = v.y;
            sA[m][kq * 4 + 2] = v.z;
            sA[m][kq * 4 + 3] = v.w;
        }
        // Load B chunk: 32 k x 96 j, j fastest (coalesced global, clean store).
        #pragma unroll
        for (int idx = tid; idx < BK * BN; idx += GEMM_THREADS) {
            int k = idx / BN, j = idx % BN;
            sB[k][j] = g_Bt[(k0 + k) * DIM + j];
        }
        __syncthreads();

        #pragma unroll
        for (int k = 0; k < BK; k++) {
            float4 bv = *(const float4*)&sB[k][tx * TN];
            float b0 = bv.x, b1 = bv.y, b2 = bv.z, b3 = bv.w;
            #pragma unroll
            for (int i = 0; i < TM; i++) {
                float a = sA[ty * TM + i][k];
                acc[i][0] += a * b0;
                acc[i][1] += a * b1;
                acc[i][2] += a * b2;
                acc[i][3] += a * b3;
            }
        }
        __syncthreads();
    }

    // Epilogue: add fused bias, store float4 per (row, col-group).
    float4 bias = *(const float4*)&g_bias[tx * TN];
    #pragma unroll
    for (int i = 0; i < TM; i++) {
        int row = rowBase + ty * TM + i;
        if (row < N_NODES) {
            float4 v;
            v.x = acc[i][0] + bias.x;
            v.y = acc[i][1] + bias.y;
            v.z = acc[i][2] + bias.z;
            v.w = acc[i][3] + bias.w;
            *(float4*)(out + (size_t)row * DIM + tx * TN) = v;
        }
    }
}

// ---------------------------------------------------------------------------
extern "C" void kernel_launch(void* const* d_in, const int* in_sizes, int n_in,
                              void* d_out, int out_size) {
    const float* x        = (const float*)d_in[0];
    const int*   ei       = (const int*)d_in[1];
    const float* W_self   = (const float*)d_in[2];
    const float* b_self   = (const float*)d_in[3];
    const float* W_neigh  = (const float*)d_in[4];
    const float* b_neigh  = (const float*)d_in[5];
    float*       out      = (float*)d_out;

    zero_kernel<<<4096, 256>>>();
    prep_kernel<<<(K2 * DIM + 255) / 256, 256>>>(W_self, W_neigh, b_self, b_neigh);

    {
        long long total = (long long)N_EDGES * 24;
        int blocks = (int)((total + 255) / 256);
        scatter_kernel<<<blocks, 256>>>(x, ei);
    }

    normalize_kernel<<<(N_NODES * 24 + 255) / 256, 256>>>();

    {
        int blocks = (N_NODES + BM - 1) / BM;   // 782
        gemm_kernel<<<blocks, GEMM_THREADS>>>(x, out);
    }
}

// round 4
// speedup vs baseline: 2.1833x; 1.0045x over previous
#include <cuda_runtime.h>

#define N_NODES 50000
#define N_EDGES 800000
#define DIM 96
#define K2 192   // concatenated K: [x | neighbor_mean]

typedef unsigned long long ull;

// Scratch (__device__ globals per allocation-free rule)
__device__ __align__(128) float g_agg[N_NODES * DIM];   // 19.2 MB
__device__ float g_deg[N_NODES];

// ---------------------------------------------------------------------------
// Kernel: edge scatter — one thread per (edge, 16B chunk). 24 chunks/edge.
// 128-bit vector reduction (red.global.add.v4.f32, sm_90+).
// ---------------------------------------------------------------------------
__global__ void scatter_kernel(const float* __restrict__ x,
                               const int* __restrict__ edge_index) {
    long long t = (long long)blockIdx.x * blockDim.x + threadIdx.x;
    int e = (int)(t / 24);
    int c = (int)(t % 24);
    if (e >= N_EDGES) return;

    int src = edge_index[e];            // edge_index[0][e]
    int dst = edge_index[N_EDGES + e];  // edge_index[1][e]

    float4 v = ((const float4*)(x + (size_t)src * DIM))[c];
    float* p = g_agg + (size_t)dst * DIM + c * 4;
    asm volatile("red.global.add.v4.f32 [%0], {%1,%2,%3,%4};"
                 :: "l"(p), "f"(v.x), "f"(v.y), "f"(v.z), "f"(v.w) : "memory");
    if (c == 0) atomicAdd(&g_deg[dst], 1.0f);
}

// ---------------------------------------------------------------------------
// GEMM: out[50000,96] = [x | g_agg/deg] @ [Ws | Wn]^T + (bs + bn)
// BM=64, BN=96, BK=32, 192 threads, 8x4 thread tile.
// Inner loop uses packed fma.rn.f32x2 (FFMA2): even/odd-k pair accumulators.
// ---------------------------------------------------------------------------
#define BM 64
#define BN 96
#define BK 32
#define TM 8
#define TN 4
#define GEMM_THREADS 192
#define APITCH (BK + 2)    // 34 floats -> 136B row stride, 8B-aligned pairs
#define BPITCH (BK / 2 + 1) // 17 float2 per row -> 136B

__device__ __forceinline__ void ffma2(ull& d, ull a, ull b) {
    asm("fma.rn.f32x2 %0, %1, %2, %0;" : "+l"(d) : "l"(a), "l"(b));
}

__global__ __launch_bounds__(GEMM_THREADS)
void gemm_kernel(const float* __restrict__ x,
                 const float* __restrict__ Ws,
                 const float* __restrict__ Wn,
                 const float* __restrict__ bs,
                 const float* __restrict__ bn,
                 float* __restrict__ out) {
    __shared__ float  sA[BM][APITCH];        // k-contiguous rows
    __shared__ float2 sB[BN][BPITCH];        // per-col k-pairs

    const int tid = threadIdx.x;
    const int tx = tid % (BN / TN);    // 0..23 column group
    const int ty = tid / (BN / TN);    // 0..7  row group
    const int rowBase = blockIdx.x * BM;

    ull acc2[TM][TN];
    #pragma unroll
    for (int i = 0; i < TM; i++)
        #pragma unroll
        for (int j = 0; j < TN; j++) acc2[i][j] = 0ULL;

    for (int k0 = 0; k0 < K2; k0 += BK) {
        const bool selfHalf = (k0 < DIM);
        const float* __restrict__ Asrc = selfHalf ? x : g_agg;
        const int kOff = selfHalf ? k0 : (k0 - DIM);

        // ---- stage A: 64 rows x 32 k = 512 float4 loads over 192 threads
        #pragma unroll
        for (int idx = tid; idx < BM * BK / 4; idx += GEMM_THREADS) {
            int m  = idx >> 3;
            int kq = idx & 7;
            int row = rowBase + m;
            float4 v = make_float4(0.f, 0.f, 0.f, 0.f);
            if (row < N_NODES) {
                v = ((const float4*)(Asrc + (size_t)row * DIM + kOff))[kq];
                if (!selfHalf) {
                    float inv = 1.0f / fmaxf(g_deg[row], 1.0f);
                    v.x *= inv; v.y *= inv; v.z *= inv; v.w *= inv;
                }
            }
            sA[m][kq * 4 + 0] = v.x;
            sA[m][kq * 4 + 1] = v.y;
            sA[m][kq * 4 + 2] = v.z;
            sA[m][kq * 4 + 3] = v.w;
        }

        // ---- stage B: [Ws|Wn] rows are k-contiguous already; pack k-pairs.
        // 96 cols x 16 pairs = 1536 float2 loads over 192 threads (8 each)
        const float* __restrict__ Bsrc = selfHalf ? Ws : Wn;
        #pragma unroll
        for (int idx = tid; idx < BN * (BK / 2); idx += GEMM_THREADS) {
            int j  = idx / (BK / 2);
            int kp = idx % (BK / 2);
            sB[j][kp] = *(const float2*)(Bsrc + (size_t)j * DIM + kOff + 2 * kp);
        }
        __syncthreads();

        #pragma unroll
        for (int kp = 0; kp < BK / 2; kp++) {
            ull a2[TM], b2[TN];
            #pragma unroll
            for (int i = 0; i < TM; i++)
                a2[i] = *(const ull*)&sA[ty * TM + i][2 * kp];
            #pragma unroll
            for (int j = 0; j < TN; j++)
                b2[j] = *(const ull*)&sB[tx * TN + j][kp];
            #pragma unroll
            for (int i = 0; i < TM; i++)
                #pragma unroll
                for (int j = 0; j < TN; j++)
                    ffma2(acc2[i][j], a2[i], b2[j]);
        }
        __syncthreads();
    }

    // ---- epilogue: reduce pair sums, add fused bias, float4 stores
    const int colBase = tx * TN;
    float4 bias;
    bias.x = bs[colBase + 0] + bn[colBase + 0];
    bias.y = bs[colBase + 1] + bn[colBase + 1];
    bias.z = bs[colBase + 2] + bn[colBase + 2];
    bias.w = bs[colBase + 3] + bn[colBase + 3];

    #pragma unroll
    for (int i = 0; i < TM; i++) {
        int row = rowBase + ty * TM + i;
        if (row < N_NODES) {
            float r[TN];
            #pragma unroll
            for (int j = 0; j < TN; j++) {
                ull u = acc2[i][j];
                float lo = __uint_as_float((unsigned)(u & 0xffffffffu));
                float hi = __uint_as_float((unsigned)(u >> 32));
                r[j] = lo + hi;
            }
            float4 v;
            v.x = r[0] + bias.x;
            v.y = r[1] + bias.y;
            v.z = r[2] + bias.z;
            v.w = r[3] + bias.w;
            *(float4*)(out + (size_t)row * DIM + colBase) = v;
        }
    }
}

// ---------------------------------------------------------------------------
extern "C" void kernel_launch(void* const* d_in, const int* in_sizes, int n_in,
                              void* d_out, int out_size) {
    const float* x        = (const float*)d_in[0];
    const int*   ei       = (const int*)d_in[1];
    const float* W_self   = (const float*)d_in[2];
    const float* b_self   = (const float*)d_in[3];
    const float* W_neigh  = (const float*)d_in[4];
    const float* b_neigh  = (const float*)d_in[5];
    float*       out      = (float*)d_out;

    static void* agg_ptr = nullptr;
    static void* deg_ptr = nullptr;
    if (!agg_ptr) {
        cudaGetSymbolAddress(&agg_ptr, g_agg);
        cudaGetSymbolAddress(&deg_ptr, g_deg);
    }

    // 1) zero scratch via memset nodes (graph-capturable)
    cudaMemsetAsync(agg_ptr, 0, (size_t)N_NODES * DIM * sizeof(float));
    cudaMemsetAsync(deg_ptr, 0, (size_t)N_NODES * sizeof(float));

    // 2) scatter: one thread per (edge, float4-chunk)
    {
        long long total = (long long)N_EDGES * 24;
        int blocks = (int)((total + 255) / 256);
        scatter_kernel<<<blocks, 256>>>(x, ei);
    }

    // 3) fused mean + dual GEMM + bias
    {
        int blocks = (N_NODES + BM - 1) / BM;   // 782
        gemm_kernel<<<blocks, GEMM_THREADS>>>(x, W_self, W_neigh,
                                              b_self, b_neigh, out);
    }
}